// round 1
// baseline (speedup 1.0000x reference)
#include <cuda_runtime.h>

// ---------------- problem constants ----------------
#define NIMG 32        // 8*4 images
#define CH   256
#define HH   36
#define WW   36
#define HWSZ 1296      // 36*36
#define MTOT (NIMG*HWSZ)   // 41472 spatial positions
#define KTOT (CH*9)        // 2304 reduction dim for 3x3 conv
#define NROI 512
#define FCK  4096          // 256*4*4
#define EPS_BN 1e-5f

// ---------------- scratch (device globals; no cudaMalloc allowed) ----------------
__device__ float g_bufA[NIMG*CH*HWSZ];   // 42.5 MB
__device__ float g_bufB[NIMG*CH*HWSZ];
__device__ float g_ft [NIMG*HWSZ*CH];    // NHWC feat
__device__ float g_Ux [NIMG*HWSZ*CH];    // NHWC cumtrapz over w
__device__ float g_Uy [NIMG*HWSZ*CH];    // NHWC cumtrapz over h
__device__ float g_T  [NIMG*HWSZ*CH];    // NHWC cumtrapz of Ux over h
__device__ float g_rf [NROI*FCK];        // pooled features (roi, c*16+cell)
__device__ float g_fc [NROI*CH];         // fc output
__device__ float g_sum[CH], g_sq[CH];    // conv BN stats
__device__ float g_fsum[CH], g_fsq[CH];  // fc BN stats

// ---------------- zero the stat accumulators ----------------
__global__ void k_zero_stats() {
    int t = threadIdx.x;
    g_sum[t]  = 0.f; g_sq[t]  = 0.f;
    g_fsum[t] = 0.f; g_fsq[t] = 0.f;
}

// ---------------- conv 3x3 as implicit GEMM ----------------
// C[m, n] = sum_k A[m,k] * B[k,n]
//   m -> (img, h, w)   n -> out channel   k = ci*9 + r*3 + s
// Block tile 128(M) x 128(N), BK=8, 256 threads, 8x8 micro-tile,
// double-buffered smem, fused bias + per-channel sum/sumsq stats.
__device__ __forceinline__ void conv_loadA(const float* __restrict__ abase,
                                           int kc, int krow, int h, int w,
                                           float ar[4])
{
#pragma unroll
    for (int i = 0; i < 4; ++i) {
        int k   = kc * 8 + krow + 2 * i;
        int ci  = k / 9;
        int rem = k - ci * 9;
        int r   = rem / 3;
        int s   = rem - r * 3;
        int hh  = h + r - 1;
        int ww  = w + s - 1;
        float v = 0.f;
        if ((unsigned)hh < HH && (unsigned)ww < WW)
            v = __ldg(abase + ci * HWSZ + hh * WW + ww);
        ar[i] = v;
    }
}

__global__ void __launch_bounds__(256, 2) k_conv(
    const float* __restrict__ Aext,   // used when mode==0
    const float* __restrict__ Wg,     // (256, 2304) row-major
    const float* __restrict__ bias,
    int mode)                         // 0: Aext->bufA, 1: bufA->bufB, 2: bufB->bufA
{
    const float* A = (mode == 0) ? Aext : (mode == 1 ? g_bufA : g_bufB);
    float* Out     = (mode == 1) ? g_bufB : g_bufA;

    __shared__ __align__(16) float As[2][8][128];
    __shared__ __align__(16) float Bs[2][8][128];
    __shared__ float sRed[256];

    const int tid = threadIdx.x;
    const int mt  = blockIdx.x * 128;
    const int nt  = blockIdx.y * 128;

    // A-load mapping: each thread loads 4 elems, fixed m, k offsets {krow, krow+2, +4, +6}
    const int m_local = tid & 127;
    const int krow    = tid >> 7;
    const int mg      = mt + m_local;
    const int nimg    = mg / HWSZ;
    const int hw      = mg - nimg * HWSZ;
    const int h       = hw / WW;
    const int w       = hw - h * WW;
    const float* abase = A + (size_t)nimg * CH * HWSZ;

    // B-load mapping: one float4 per thread
    const int nb = tid >> 1;
    const int kb = (tid & 1) * 4;
    const float* bptr = Wg + (size_t)(nt + nb) * KTOT + kb;

    // compute mapping
    const int tm = tid & 15;   // m micro index (stride 16)
    const int tn = tid >> 4;   // n micro group (8 channels)

    float acc[8][8];
#pragma unroll
    for (int i = 0; i < 8; ++i)
#pragma unroll
        for (int j = 0; j < 8; ++j) acc[i][j] = 0.f;

    float ar[4];
    float4 br;

    // prologue: chunk 0 -> buffer 0
    conv_loadA(abase, 0, krow, h, w, ar);
    br = *(const float4*)bptr;
#pragma unroll
    for (int i = 0; i < 4; ++i) As[0][krow + 2 * i][m_local] = ar[i];
    Bs[0][kb + 0][nb] = br.x;
    Bs[0][kb + 1][nb] = br.y;
    Bs[0][kb + 2][nb] = br.z;
    Bs[0][kb + 3][nb] = br.w;

    int buf = 0;
    const int NCHUNK = KTOT / 8;  // 288
    for (int kc = 0; kc < NCHUNK; ++kc) {
        __syncthreads();
        const bool pf = (kc + 1) < NCHUNK;
        if (pf) {
            conv_loadA(abase, kc + 1, krow, h, w, ar);
            br = *(const float4*)(bptr + (size_t)(kc + 1) * 8);
        }
#pragma unroll
        for (int kk = 0; kk < 8; ++kk) {
            float a[8];
#pragma unroll
            for (int i = 0; i < 8; ++i) a[i] = As[buf][kk][tm + 16 * i];
            float4 b0 = *(const float4*)&Bs[buf][kk][tn * 8];
            float4 b1 = *(const float4*)&Bs[buf][kk][tn * 8 + 4];
            float b[8] = {b0.x, b0.y, b0.z, b0.w, b1.x, b1.y, b1.z, b1.w};
#pragma unroll
            for (int i = 0; i < 8; ++i)
#pragma unroll
                for (int j = 0; j < 8; ++j)
                    acc[i][j] = fmaf(a[i], b[j], acc[i][j]);
        }
        if (pf) {
            const int nbuf = buf ^ 1;
#pragma unroll
            for (int i = 0; i < 4; ++i) As[nbuf][krow + 2 * i][m_local] = ar[i];
            Bs[nbuf][kb + 0][nb] = br.x;
            Bs[nbuf][kb + 1][nb] = br.y;
            Bs[nbuf][kb + 2][nb] = br.z;
            Bs[nbuf][kb + 3][nb] = br.w;
            buf = nbuf;
        }
    }

    // epilogue: bias, NCHW store, per-channel stats
    int ni2[8], hw2[8];
#pragma unroll
    for (int i = 0; i < 8; ++i) {
        int m  = mt + tm + 16 * i;
        ni2[i] = m / HWSZ;
        hw2[i] = m - ni2[i] * HWSZ;
    }
    float s1a[8], s2a[8];
#pragma unroll
    for (int j = 0; j < 8; ++j) {
        const int c  = nt + tn * 8 + j;
        const float bv = __ldg(&bias[c]);
        float s1 = 0.f, s2 = 0.f;
#pragma unroll
        for (int i = 0; i < 8; ++i) {
            float v = acc[i][j] + bv;
            Out[((size_t)ni2[i] * CH + c) * HWSZ + hw2[i]] = v;
            s1 += v;
            s2 += v * v;
        }
        s1a[j] = s1; s2a[j] = s2;
    }
    __syncthreads();
    sRed[tid] = 0.f;
    __syncthreads();
#pragma unroll
    for (int j = 0; j < 8; ++j) {
        const int cl = tn * 8 + j;
        atomicAdd(&sRed[cl], s1a[j]);
        atomicAdd(&sRed[128 + cl], s2a[j]);
    }
    __syncthreads();
    if (tid < 128) {
        atomicAdd(&g_sum[nt + tid], sRed[tid]);
        atomicAdd(&g_sq [nt + tid], sRed[128 + tid]);
    }
}

// ---------------- BN (batch stats) + ReLU, in place ----------------
__global__ void k_bnrelu(const float* __restrict__ gm,
                         const float* __restrict__ bt,
                         int useB)
{
    float* X = useB ? g_bufB : g_bufA;
    const float invN = 1.0f / (float)MTOT;
    int i4 = blockIdx.x * blockDim.x + threadIdx.x;  // float4 index
    int c  = ((i4 * 4) / HWSZ) & (CH - 1);
    float m  = g_sum[c] * invN;
    float v  = g_sq[c] * invN - m * m;
    float sc = rsqrtf(v + EPS_BN) * __ldg(&gm[c]);
    float sh = __ldg(&bt[c]) - m * sc;
    float4 x = ((float4*)X)[i4];
    x.x = fmaxf(fmaf(x.x, sc, sh), 0.f);
    x.y = fmaxf(fmaf(x.y, sc, sh), 0.f);
    x.z = fmaxf(fmaf(x.z, sc, sh), 0.f);
    x.w = fmaxf(fmaf(x.w, sc, sh), 0.f);
    ((float4*)X)[i4] = x;
}

// ---------------- NCHW -> NHWC transpose of final activation ----------------
__global__ void k_transpose()
{
    __shared__ float s[32][33];
    const int cb = blockIdx.x;  // 0..7
    const int n  = blockIdx.y;  // 0..31
    const int pb = blockIdx.z;  // 0..40
    const int tx = threadIdx.x, ty = threadIdx.y;  // (32, 8)
    const int p0 = pb * 32;
#pragma unroll
    for (int yy = 0; yy < 4; ++yy) {
        int c = cb * 32 + ty + yy * 8;
        int p = p0 + tx;
        s[ty + yy * 8][tx] = (p < HWSZ) ? g_bufA[((size_t)n * CH + c) * HWSZ + p] : 0.f;
    }
    __syncthreads();
#pragma unroll
    for (int yy = 0; yy < 4; ++yy) {
        int p = p0 + ty + yy * 8;
        int c = cb * 32 + tx;
        if (p < HWSZ)
            g_ft[((size_t)n * HWSZ + p) * CH + c] = s[tx][ty + yy * 8];
    }
}

// ---------------- cumtrapz along w (Ux), NHWC ----------------
__global__ void k_cumx()
{
    const int nh = blockIdx.x;     // n*36 + h
    const int c  = threadIdx.x;
    size_t base = ((size_t)nh * WW) * CH + c;
    float prev = g_ft[base];
    float u = 0.f;
    g_Ux[base] = 0.f;
    for (int w = 1; w < WW; ++w) {
        float f = g_ft[base + (size_t)w * CH];
        u += 0.5f * (prev + f);
        g_Ux[base + (size_t)w * CH] = u;
        prev = f;
    }
}

// ---------------- cumtrapz along h: Uy from feat, T from Ux ----------------
__global__ void k_cumy()
{
    const int nw = blockIdx.x;     // n*36 + w
    const int n  = nw / WW;
    const int w  = nw - n * WW;
    const int c  = threadIdx.x;
    size_t base   = ((size_t)n * HWSZ + w) * CH + c;
    size_t stride = (size_t)WW * CH;
    float pf = g_ft[base], pu = g_Ux[base];
    float uy = 0.f, tt = 0.f;
    g_Uy[base] = 0.f;
    g_T[base]  = 0.f;
    for (int hh = 1; hh < HH; ++hh) {
        float f = g_ft[base + hh * stride];
        float u = g_Ux[base + hh * stride];
        uy += 0.5f * (pf + f);
        tt += 0.5f * (pu + u);
        g_Uy[base + hh * stride] = uy;
        g_T [base + hh * stride] = tt;
        pf = f; pu = u;
    }
}

// ---------------- PrRoI pooling: one block per ROI, thread = channel ----------------
__global__ void k_pool(const float* __restrict__ props)
{
    const int p = blockIdx.x;    // 0..511
    const int c = threadIdx.x;   // 0..255
    const float px = __ldg(&props[p * 4 + 0]);
    const float py = __ldg(&props[p * 4 + 1]);
    const float pw = __ldg(&props[p * 4 + 2]);
    const float ph = __ldg(&props[p * 4 + 3]);
    const float x1 = px * 20.f;
    const float y1 = py * 20.f;
    const float x2 = (px + pw) * 20.f;
    const float y2 = (py + ph) * 20.f;
    const float bw = (x2 - x1) * 0.25f;
    const float bh = (y2 - y1) * 0.25f;

    int   wx[5], hy[5];
    float px0[5], px1[5], py0[5], py1[5];
#pragma unroll
    for (int i = 0; i < 5; ++i) {
        float xs = fminf(fmaxf(x1 + bw * (float)i, 0.f), 35.f);
        int w0 = min((int)floorf(xs), 34);
        float sx = xs - (float)w0;
        float q = 0.5f * sx * sx;
        px1[i] = q; px0[i] = sx - q; wx[i] = w0;

        float ys = fminf(fmaxf(y1 + bh * (float)i, 0.f), 35.f);
        int h0 = min((int)floorf(ys), 34);
        float sy = ys - (float)h0;
        float r = 0.5f * sy * sy;
        py1[i] = r; py0[i] = sy - r; hy[i] = h0;
    }

    const int b = p >> 4;
    float G[5][5];
#pragma unroll
    for (int iy = 0; iy < 5; ++iy) {
#pragma unroll
        for (int ix = 0; ix < 5; ++ix) {
            size_t i00 = (((size_t)b * HH + hy[iy]) * WW + wx[ix]) * CH + c;
            size_t i01 = i00 + CH;
            size_t i10 = i00 + (size_t)WW * CH;
            size_t i11 = i10 + CH;
            G[iy][ix] = g_T[i00]
                      + g_Uy[i00] * px0[ix] + g_Uy[i01] * px1[ix]
                      + py0[iy] * (g_Ux[i00] + g_ft[i00] * px0[ix] + g_ft[i01] * px1[ix])
                      + py1[iy] * (g_Ux[i10] + g_ft[i10] * px0[ix] + g_ft[i11] * px1[ix]);
        }
    }
    const float area = bw * bh;
    const float inv  = (area > 1e-8f) ? (1.f / fmaxf(area, 1e-8f)) : 0.f;
    float* out = g_rf + (size_t)p * FCK + c * 16;
#pragma unroll
    for (int iy = 0; iy < 4; ++iy)
#pragma unroll
        for (int ix = 0; ix < 4; ++ix)
            out[iy * 4 + ix] =
                (G[iy + 1][ix + 1] - G[iy][ix + 1] - G[iy + 1][ix] + G[iy][ix]) * inv;
}

// ---------------- FC GEMM: (512 x 4096) @ (4096 x 256) + bias, fused stats ----------------
__global__ void __launch_bounds__(256) k_fc(const float* __restrict__ Wfc,
                                            const float* __restrict__ bias)
{
    __shared__ float As[16][65];
    __shared__ float Bs[16][65];
    __shared__ float sRed[128];

    const int tid = threadIdx.x;
    const int mt  = blockIdx.x * 64;
    const int nt  = blockIdx.y * 64;
    const int lr  = tid >> 2;          // 0..63
    const int lk  = (tid & 3) * 4;     // 0,4,8,12
    const int tm  = tid & 15;
    const int tn  = tid >> 4;

    float acc[4][4];
#pragma unroll
    for (int i = 0; i < 4; ++i)
#pragma unroll
        for (int j = 0; j < 4; ++j) acc[i][j] = 0.f;

    for (int kc = 0; kc < FCK / 16; ++kc) {
        float4 av = *(const float4*)&g_rf[(size_t)(mt + lr) * FCK + kc * 16 + lk];
        float4 bv = *(const float4*)&Wfc [(size_t)(nt + lr) * FCK + kc * 16 + lk];
        __syncthreads();
        As[lk + 0][lr] = av.x; As[lk + 1][lr] = av.y;
        As[lk + 2][lr] = av.z; As[lk + 3][lr] = av.w;
        Bs[lk + 0][lr] = bv.x; Bs[lk + 1][lr] = bv.y;
        Bs[lk + 2][lr] = bv.z; Bs[lk + 3][lr] = bv.w;
        __syncthreads();
#pragma unroll
        for (int kk = 0; kk < 16; ++kk) {
            float a[4], b[4];
#pragma unroll
            for (int i = 0; i < 4; ++i) a[i] = As[kk][tm + 16 * i];
#pragma unroll
            for (int j = 0; j < 4; ++j) b[j] = Bs[kk][tn * 4 + j];
#pragma unroll
            for (int i = 0; i < 4; ++i)
#pragma unroll
                for (int j = 0; j < 4; ++j)
                    acc[i][j] = fmaf(a[i], b[j], acc[i][j]);
        }
    }

    float s1a[4], s2a[4];
#pragma unroll
    for (int j = 0; j < 4; ++j) {
        const int c = nt + tn * 4 + j;
        const float bv = __ldg(&bias[c]);
        float s1 = 0.f, s2 = 0.f;
#pragma unroll
        for (int i = 0; i < 4; ++i) {
            const int m = mt + tm + 16 * i;
            float v = acc[i][j] + bv;
            g_fc[(size_t)m * CH + c] = v;
            s1 += v;
            s2 += v * v;
        }
        s1a[j] = s1; s2a[j] = s2;
    }
    __syncthreads();
    if (tid < 128) sRed[tid] = 0.f;
    __syncthreads();
#pragma unroll
    for (int j = 0; j < 4; ++j) {
        const int cl = tn * 4 + j;
        atomicAdd(&sRed[cl], s1a[j]);
        atomicAdd(&sRed[64 + cl], s2a[j]);
    }
    __syncthreads();
    if (tid < 64) {
        atomicAdd(&g_fsum[nt + tid], sRed[tid]);
        atomicAdd(&g_fsq [nt + tid], sRed[64 + tid]);
    }
}

// ---------------- FC BN + ReLU + IoU head ----------------
__global__ void k_fcbn_iou(const float* __restrict__ gm,
                           const float* __restrict__ bt,
                           const float* __restrict__ iw,
                           const float* __restrict__ ib,
                           float* __restrict__ out)
{
    __shared__ float sred[8];
    const int p = blockIdx.x;
    const int c = threadIdx.x;
    const float invN = 1.f / (float)NROI;
    float m  = g_fsum[c] * invN;
    float v  = g_fsq[c] * invN - m * m;
    float sc = rsqrtf(v + EPS_BN) * __ldg(&gm[c]);
    float sh = __ldg(&bt[c]) - m * sc;
    float x  = fmaxf(fmaf(g_fc[(size_t)p * CH + c], sc, sh), 0.f);
    float t  = x * __ldg(&iw[c]);
#pragma unroll
    for (int o = 16; o; o >>= 1) t += __shfl_xor_sync(0xffffffffu, t, o);
    if ((c & 31) == 0) sred[c >> 5] = t;
    __syncthreads();
    if (c == 0) {
        float s = 0.f;
#pragma unroll
        for (int i = 0; i < 8; ++i) s += sred[i];
        out[p] = s + __ldg(&ib[0]);
    }
}

// ---------------- launch sequence ----------------
extern "C" void kernel_launch(void* const* d_in, const int* in_sizes, int n_in,
                              void* d_out, int out_size)
{
    const float* feat  = (const float*)d_in[0];
    const float* props = (const float*)d_in[1];
    const float* c1w = (const float*)d_in[2];
    const float* c1b = (const float*)d_in[3];
    const float* b1g = (const float*)d_in[4];
    const float* b1b = (const float*)d_in[5];
    const float* c2w = (const float*)d_in[6];
    const float* c2b = (const float*)d_in[7];
    const float* b2g = (const float*)d_in[8];
    const float* b2b = (const float*)d_in[9];
    const float* c3w = (const float*)d_in[10];
    const float* c3b = (const float*)d_in[11];
    const float* b3g = (const float*)d_in[12];
    const float* b3b = (const float*)d_in[13];
    const float* fcw = (const float*)d_in[14];
    const float* fcb = (const float*)d_in[15];
    const float* fbg = (const float*)d_in[16];
    const float* fbb = (const float*)d_in[17];
    const float* iw  = (const float*)d_in[18];
    const float* ib  = (const float*)d_in[19];
    float* out = (float*)d_out;

    const dim3 convGrid(MTOT / 128, 2);
    const int bnBlocks = (NIMG * CH * HWSZ / 4) / 256;   // 10368

    // conv1
    k_zero_stats<<<1, 256>>>();
    k_conv<<<convGrid, 256>>>(feat, c1w, c1b, 0);
    k_bnrelu<<<bnBlocks, 256>>>(b1g, b1b, 0);
    // conv2
    k_zero_stats<<<1, 256>>>();
    k_conv<<<convGrid, 256>>>(feat, c2w, c2b, 1);
    k_bnrelu<<<bnBlocks, 256>>>(b2g, b2b, 1);
    // conv3
    k_zero_stats<<<1, 256>>>();
    k_conv<<<convGrid, 256>>>(feat, c3w, c3b, 2);
    k_bnrelu<<<bnBlocks, 256>>>(b3g, b3b, 0);

    // integral images (NHWC)
    k_transpose<<<dim3(8, 32, 41), dim3(32, 8)>>>();
    k_cumx<<<NIMG * HH, 256>>>();
    k_cumy<<<NIMG * WW, 256>>>();

    // PrRoI pooling
    k_pool<<<NROI, 256>>>(props);

    // FC + BN + IoU
    k_zero_stats<<<1, 256>>>();
    k_fc<<<dim3(NROI / 64, CH / 64), 256>>>(fcw, fcb);
    k_fcbn_iou<<<NROI, 256>>>(fbg, fbb, iw, ib, out);
}

// round 3
// speedup vs baseline: 1.5482x; 1.5482x over previous
#include <cuda_runtime.h>
#include <cstdint>

// ---------------- problem constants ----------------
#define NIMG 32
#define CH   256
#define HH   36
#define WW   36
#define HWSZ 1296
#define MTOT (NIMG*HWSZ)   // 41472
#define KTOT (CH*9)        // 2304
#define NROI 512
#define FCK  4096
#define EPS_BN 1e-5f
#define CHW  (CH*HWSZ)     // 331776

// ---------------- scratch ----------------
__device__ float g_bufA[NIMG*CH*HWSZ];
__device__ float g_bufB[NIMG*CH*HWSZ];   // unused spare
__device__ float g_ft [NIMG*HWSZ*CH];    // conv phase: A_hi   | later: NHWC feat
__device__ float g_Ux [NIMG*HWSZ*CH];    // conv phase: A_lo   | later: cumtrapz w
__device__ float g_Uy [NIMG*HWSZ*CH];
__device__ float g_T  [NIMG*HWSZ*CH];
__device__ float g_wtH[KTOT*CH];         // weights k-major, tf32 hi
__device__ float g_wtL[KTOT*CH];         // weights k-major, tf32 lo
__device__ float g_rf [NROI*FCK];
__device__ float g_fc [NROI*CH];
__device__ float g_sum[CH], g_sq[CH];
__device__ float g_fsum[CH], g_fsq[CH];

// ---------------- helpers ----------------
__device__ __forceinline__ uint32_t smem_u32(const void* p) {
    uint32_t a;
    asm("{ .reg .u64 t; cvta.to.shared.u64 t, %1; cvt.u32.u64 %0, t; }" : "=r"(a) : "l"(p));
    return a;
}
__device__ __forceinline__ float tf32f(float v) {
    uint32_t u;
    asm("cvt.rna.tf32.f32 %0, %1;" : "=r"(u) : "f"(v));
    return __uint_as_float(u);
}
__device__ __forceinline__ void mma8(float d[4], const uint32_t a[4], const uint32_t b[2]) {
    asm volatile("mma.sync.aligned.m16n8k8.row.col.f32.tf32.tf32.f32 "
        "{%0,%1,%2,%3},{%4,%5,%6,%7},{%8,%9},{%0,%1,%2,%3};"
        : "+f"(d[0]), "+f"(d[1]), "+f"(d[2]), "+f"(d[3])
        : "r"(a[0]), "r"(a[1]), "r"(a[2]), "r"(a[3]), "r"(b[0]), "r"(b[1]));
}
__device__ __forceinline__ void cp4(uint32_t dst, const void* src, uint32_t sz) {
    asm volatile("cp.async.ca.shared.global [%0], [%1], 4, %2;" :: "r"(dst), "l"(src), "r"(sz));
}
__device__ __forceinline__ void cp16(uint32_t dst, const void* src) {
    asm volatile("cp.async.cg.shared.global [%0], [%1], 16;" :: "r"(dst), "l"(src));
}
#define CP_COMMIT() asm volatile("cp.async.commit_group;" ::: "memory")
#define CP_WAIT0()  asm volatile("cp.async.wait_group 0;"  ::: "memory")

// ---------------- zero stats ----------------
__global__ void k_zero_stats() {
    int t = threadIdx.x;
    g_sum[t]  = 0.f; g_sq[t]  = 0.f;
    g_fsum[t] = 0.f; g_fsq[t] = 0.f;
}

// ---------------- weight prep: transpose to k-major (k = tap*256+ci), tf32 split ----------------
__global__ void k_wprep(const float* __restrict__ W) {
    int idx = blockIdx.x * 256 + threadIdx.x;       // idx = kg*256 + n
    int n  = idx & 255;
    int kg = idx >> 8;
    int ci = kg & 255;
    int tap = kg >> 8;
    float v  = __ldg(&W[(size_t)n * KTOT + ci * 9 + tap]);
    float hi = tf32f(v);
    g_wtH[idx] = hi;
    g_wtL[idx] = tf32f(v - hi);
}

// ---------------- conv1 input prep: tf32 split of feat ----------------
__global__ void k_cvtA(const float* __restrict__ feat) {
    int i = blockIdx.x * 256 + threadIdx.x;         // 41472 blocks
    float v  = __ldg(&feat[i]);
    float hi = tf32f(v);
    g_ft[i] = hi;
    g_Ux[i] = tf32f(v - hi);
}

// ================= mma.sync tf32x3 implicit-GEMM conv =================
// CTA 128(M)x128(N); 4 warps, warp tile 64x64 (mf=4, nf=8); K in 72 chunks of 32.
// K order: k = tap*256 + ci. A from split (g_ft hi, g_Ux lo); W from g_wtH/L.
// Out: raw fp32 -> g_bufA, fused per-channel stats.
__global__ void __launch_bounds__(128, 2) k_conv_m(const float* __restrict__ bias)
{
    extern __shared__ float dyn[];
    __shared__ float sRed1[128], sRed2[128];
    float* AsH = dyn;            // [32][136]
    float* AsL = dyn + 4352;
    float* BsH = dyn + 8704;
    float* BsL = dyn + 13056;
    const uint32_t sb   = smem_u32(dyn);
    const uint32_t AsHb = sb, AsLb = sb + 17408, BsHb = sb + 34816, BsLb = sb + 52224;

    const int tid  = threadIdx.x;
    const int lane = tid & 31, wid = tid >> 5;
    const int mt   = blockIdx.x * 128, nt = blockIdx.y * 128;
    const int wm   = (wid >> 1) * 64, wn = (wid & 1) * 64;
    const int g    = lane >> 2, c0 = lane & 3;

    sRed1[tid] = 0.f; sRed2[tid] = 0.f;

    // A-fill: this thread owns m = mt + tid, all 32 k's of a chunk
    const int mA    = mt + tid;
    const int nimgA = mA / HWSZ;
    const int remA  = mA - nimgA * HWSZ;
    const int hA    = remA / WW;
    const int wA    = remA - hA * WW;

    // B-fill: k = i*4 + bk, 16B of n
    const int bk = tid >> 5;
    const int n4 = (tid & 31) * 4;

    float acc[4][8][4];
#pragma unroll
    for (int a = 0; a < 4; ++a)
#pragma unroll
        for (int b = 0; b < 8; ++b)
#pragma unroll
            for (int c = 0; c < 4; ++c) acc[a][b][c] = 0.f;

    for (int tap = 0; tap < 9; ++tap) {
        const int dr = tap / 3 - 1, ds = tap % 3 - 1;
        const int hh = hA + dr, ww = wA + ds;
        const bool valid = ((unsigned)hh < HH) && ((unsigned)ww < WW);
        const uint32_t sz = valid ? 4u : 0u;
        const int sA = valid ? (nimgA * CHW + hh * WW + ww) : 0;

        for (int cc = 0; cc < 8; ++cc) {
            const int chunk = tap * 8 + cc;
            __syncthreads();     // previous compute done, smem free
            // ---- A fill: 32 k's x (hi, lo), 4B cp.async each ----
            {
                const float* ph = g_ft + sA + (size_t)(cc * 32) * HWSZ;
                const float* pl = g_Ux + sA + (size_t)(cc * 32) * HWSZ;
                uint32_t dh = AsHb + tid * 4;
                uint32_t dl = AsLb + tid * 4;
#pragma unroll 8
                for (int i = 0; i < 32; ++i) {
                    cp4(dh, ph, sz);
                    cp4(dl, pl, sz);
                    ph += HWSZ; pl += HWSZ;
                    dh += 544;  dl += 544;
                }
            }
            // ---- B fill: 8 x 16B x (hi, lo) ----
            {
#pragma unroll
                for (int i = 0; i < 8; ++i) {
                    const int k = i * 4 + bk;
                    const size_t so = (size_t)(chunk * 32 + k) * 256 + nt + n4;
                    cp16(BsHb + k * 544 + n4 * 4, g_wtH + so);
                    cp16(BsLb + k * 544 + n4 * 4, g_wtL + so);
                }
            }
            CP_COMMIT();
            CP_WAIT0();
            __syncthreads();
            // ---- compute: 4 k8 steps x (hihi + hilo + lohi) ----
#pragma unroll
            for (int kk = 0; kk < 4; ++kk) {
                const int r0 = (kk * 8 + c0) * 136;
                const int r1 = r0 + 4 * 136;
                uint32_t ah[4][4], al[4][4], bh[8][2], bl[8][2];
#pragma unroll
                for (int mf = 0; mf < 4; ++mf) {
                    const int col = wm + mf * 16 + g;
                    ah[mf][0] = __float_as_uint(AsH[r0 + col]);
                    ah[mf][1] = __float_as_uint(AsH[r0 + col + 8]);
                    ah[mf][2] = __float_as_uint(AsH[r1 + col]);
                    ah[mf][3] = __float_as_uint(AsH[r1 + col + 8]);
                    al[mf][0] = __float_as_uint(AsL[r0 + col]);
                    al[mf][1] = __float_as_uint(AsL[r0 + col + 8]);
                    al[mf][2] = __float_as_uint(AsL[r1 + col]);
                    al[mf][3] = __float_as_uint(AsL[r1 + col + 8]);
                }
#pragma unroll
                for (int nf = 0; nf < 8; ++nf) {
                    const int col = wn + nf * 8 + g;
                    bh[nf][0] = __float_as_uint(BsH[r0 + col]);
                    bh[nf][1] = __float_as_uint(BsH[r1 + col]);
                    bl[nf][0] = __float_as_uint(BsL[r0 + col]);
                    bl[nf][1] = __float_as_uint(BsL[r1 + col]);
                }
#pragma unroll
                for (int mf = 0; mf < 4; ++mf)
#pragma unroll
                    for (int nf = 0; nf < 8; ++nf) {
                        mma8(acc[mf][nf], ah[mf], bh[nf]);
                        mma8(acc[mf][nf], ah[mf], bl[nf]);
                        mma8(acc[mf][nf], al[mf], bh[nf]);
                    }
            }
        }
    }

    // ---------------- epilogue: bias, NCHW store, fused stats ----------------
    float s1[16], s2[16];
#pragma unroll
    for (int i = 0; i < 16; ++i) { s1[i] = 0.f; s2[i] = 0.f; }

#pragma unroll
    for (int mf = 0; mf < 4; ++mf) {
#pragma unroll
        for (int rr = 0; rr < 2; ++rr) {
            const int m    = mt + wm + mf * 16 + g + rr * 8;
            const int nimg = m / HWSZ;
            const int hw   = m - nimg * HWSZ;
            float* orow = g_bufA + (size_t)nimg * CHW + hw;
#pragma unroll
            for (int nf = 0; nf < 8; ++nf) {
                const int c = nt + wn + nf * 8 + c0 * 2;
                const float v0 = acc[mf][nf][rr * 2]     + __ldg(&bias[c]);
                const float v1 = acc[mf][nf][rr * 2 + 1] + __ldg(&bias[c + 1]);
                orow[(size_t)c * HWSZ]       = v0;
                orow[(size_t)(c + 1) * HWSZ] = v1;
                s1[nf * 2]     += v0; s2[nf * 2]     += v0 * v0;
                s1[nf * 2 + 1] += v1; s2[nf * 2 + 1] += v1 * v1;
            }
        }
    }
    __syncthreads();
#pragma unroll
    for (int nf = 0; nf < 8; ++nf) {
        const int cl = wn + nf * 8 + c0 * 2;
        atomicAdd(&sRed1[cl],     s1[nf * 2]);
        atomicAdd(&sRed2[cl],     s2[nf * 2]);
        atomicAdd(&sRed1[cl + 1], s1[nf * 2 + 1]);
        atomicAdd(&sRed2[cl + 1], s2[nf * 2 + 1]);
    }
    __syncthreads();
    atomicAdd(&g_sum[nt + tid], sRed1[tid]);
    atomicAdd(&g_sq [nt + tid], sRed2[tid]);
}

// ---------------- BN + ReLU, output tf32-split for next conv ----------------
__global__ void k_bnrelu_split(const float* __restrict__ gm,
                               const float* __restrict__ bt)
{
    int i = blockIdx.x * 256 + threadIdx.x;
    const float invN = 1.0f / (float)MTOT;
    int c = (i / HWSZ) & (CH - 1);
    float m  = g_sum[c] * invN;
    float v  = g_sq[c] * invN - m * m;
    float sc = rsqrtf(v + EPS_BN) * __ldg(&gm[c]);
    float sh = __ldg(&bt[c]) - m * sc;
    float y  = fmaxf(fmaf(g_bufA[i], sc, sh), 0.f);
    float hi = tf32f(y);
    g_ft[i] = hi;
    g_Ux[i] = tf32f(y - hi);
}

// ---------------- BN + ReLU in place (final layer) ----------------
__global__ void k_bnrelu_ip(const float* __restrict__ gm,
                            const float* __restrict__ bt)
{
    const float invN = 1.0f / (float)MTOT;
    int i4 = blockIdx.x * blockDim.x + threadIdx.x;
    int c  = ((i4 * 4) / HWSZ) & (CH - 1);
    float m  = g_sum[c] * invN;
    float v  = g_sq[c] * invN - m * m;
    float sc = rsqrtf(v + EPS_BN) * __ldg(&gm[c]);
    float sh = __ldg(&bt[c]) - m * sc;
    float4 x = ((float4*)g_bufA)[i4];
    x.x = fmaxf(fmaf(x.x, sc, sh), 0.f);
    x.y = fmaxf(fmaf(x.y, sc, sh), 0.f);
    x.z = fmaxf(fmaf(x.z, sc, sh), 0.f);
    x.w = fmaxf(fmaf(x.w, sc, sh), 0.f);
    ((float4*)g_bufA)[i4] = x;
}

// ---------------- NCHW -> NHWC transpose ----------------
__global__ void k_transpose()
{
    __shared__ float s[32][33];
    const int cb = blockIdx.x;
    const int n  = blockIdx.y;
    const int pb = blockIdx.z;
    const int tx = threadIdx.x, ty = threadIdx.y;
    const int p0 = pb * 32;
#pragma unroll
    for (int yy = 0; yy < 4; ++yy) {
        int c = cb * 32 + ty + yy * 8;
        int p = p0 + tx;
        s[ty + yy * 8][tx] = (p < HWSZ) ? g_bufA[((size_t)n * CH + c) * HWSZ + p] : 0.f;
    }
    __syncthreads();
#pragma unroll
    for (int yy = 0; yy < 4; ++yy) {
        int p = p0 + ty + yy * 8;
        int c = cb * 32 + tx;
        if (p < HWSZ)
            g_ft[((size_t)n * HWSZ + p) * CH + c] = s[tx][ty + yy * 8];
    }
}

// ---------------- cumtrapz along w ----------------
__global__ void k_cumx()
{
    const int nh = blockIdx.x;
    const int c  = threadIdx.x;
    size_t base = ((size_t)nh * WW) * CH + c;
    float prev = g_ft[base];
    float u = 0.f;
    g_Ux[base] = 0.f;
    for (int w = 1; w < WW; ++w) {
        float f = g_ft[base + (size_t)w * CH];
        u += 0.5f * (prev + f);
        g_Ux[base + (size_t)w * CH] = u;
        prev = f;
    }
}

// ---------------- cumtrapz along h ----------------
__global__ void k_cumy()
{
    const int nw = blockIdx.x;
    const int n  = nw / WW;
    const int w  = nw - n * WW;
    const int c  = threadIdx.x;
    size_t base   = ((size_t)n * HWSZ + w) * CH + c;
    size_t stride = (size_t)WW * CH;
    float pf = g_ft[base], pu = g_Ux[base];
    float uy = 0.f, tt = 0.f;
    g_Uy[base] = 0.f;
    g_T[base]  = 0.f;
    for (int hh = 1; hh < HH; ++hh) {
        float f = g_ft[base + hh * stride];
        float u = g_Ux[base + hh * stride];
        uy += 0.5f * (pf + f);
        tt += 0.5f * (pu + u);
        g_Uy[base + hh * stride] = uy;
        g_T [base + hh * stride] = tt;
        pf = f; pu = u;
    }
}

// ---------------- PrRoI pooling ----------------
__global__ void k_pool(const float* __restrict__ props)
{
    const int p = blockIdx.x;
    const int c = threadIdx.x;
    const float px = __ldg(&props[p * 4 + 0]);
    const float py = __ldg(&props[p * 4 + 1]);
    const float pw = __ldg(&props[p * 4 + 2]);
    const float ph = __ldg(&props[p * 4 + 3]);
    const float x1 = px * 20.f;
    const float y1 = py * 20.f;
    const float x2 = (px + pw) * 20.f;
    const float y2 = (py + ph) * 20.f;
    const float bw = (x2 - x1) * 0.25f;
    const float bh = (y2 - y1) * 0.25f;

    int   wx[5], hy[5];
    float px0[5], px1[5], py0[5], py1[5];
#pragma unroll
    for (int i = 0; i < 5; ++i) {
        float xs = fminf(fmaxf(x1 + bw * (float)i, 0.f), 35.f);
        int w0 = min((int)floorf(xs), 34);
        float sx = xs - (float)w0;
        float q = 0.5f * sx * sx;
        px1[i] = q; px0[i] = sx - q; wx[i] = w0;

        float ys = fminf(fmaxf(y1 + bh * (float)i, 0.f), 35.f);
        int h0 = min((int)floorf(ys), 34);
        float sy = ys - (float)h0;
        float r = 0.5f * sy * sy;
        py1[i] = r; py0[i] = sy - r; hy[i] = h0;
    }

    const int b = p >> 4;
    float G[5][5];
#pragma unroll
    for (int iy = 0; iy < 5; ++iy) {
#pragma unroll
        for (int ix = 0; ix < 5; ++ix) {
            size_t i00 = (((size_t)b * HH + hy[iy]) * WW + wx[ix]) * CH + c;
            size_t i01 = i00 + CH;
            size_t i10 = i00 + (size_t)WW * CH;
            size_t i11 = i10 + CH;
            G[iy][ix] = g_T[i00]
                      + g_Uy[i00] * px0[ix] + g_Uy[i01] * px1[ix]
                      + py0[iy] * (g_Ux[i00] + g_ft[i00] * px0[ix] + g_ft[i01] * px1[ix])
                      + py1[iy] * (g_Ux[i10] + g_ft[i10] * px0[ix] + g_ft[i11] * px1[ix]);
        }
    }
    const float area = bw * bh;
    const float inv  = (area > 1e-8f) ? (1.f / fmaxf(area, 1e-8f)) : 0.f;
    float* out = g_rf + (size_t)p * FCK + c * 16;
#pragma unroll
    for (int iy = 0; iy < 4; ++iy)
#pragma unroll
        for (int ix = 0; ix < 4; ++ix)
            out[iy * 4 + ix] =
                (G[iy + 1][ix + 1] - G[iy][ix + 1] - G[iy + 1][ix] + G[iy][ix]) * inv;
}

// ---------------- FC GEMM + fused stats ----------------
__global__ void __launch_bounds__(256) k_fc(const float* __restrict__ Wfc,
                                            const float* __restrict__ bias)
{
    __shared__ float As[16][65];
    __shared__ float Bs[16][65];
    __shared__ float sRed[128];

    const int tid = threadIdx.x;
    const int mt  = blockIdx.x * 64;
    const int nt  = blockIdx.y * 64;
    const int lr  = tid >> 2;
    const int lk  = (tid & 3) * 4;
    const int tm  = tid & 15;
    const int tn  = tid >> 4;

    float acc[4][4];
#pragma unroll
    for (int i = 0; i < 4; ++i)
#pragma unroll
        for (int j = 0; j < 4; ++j) acc[i][j] = 0.f;

    for (int kc = 0; kc < FCK / 16; ++kc) {
        float4 av = *(const float4*)&g_rf[(size_t)(mt + lr) * FCK + kc * 16 + lk];
        float4 bv = *(const float4*)&Wfc [(size_t)(nt + lr) * FCK + kc * 16 + lk];
        __syncthreads();
        As[lk + 0][lr] = av.x; As[lk + 1][lr] = av.y;
        As[lk + 2][lr] = av.z; As[lk + 3][lr] = av.w;
        Bs[lk + 0][lr] = bv.x; Bs[lk + 1][lr] = bv.y;
        Bs[lk + 2][lr] = bv.z; Bs[lk + 3][lr] = bv.w;
        __syncthreads();
#pragma unroll
        for (int kk = 0; kk < 16; ++kk) {
            float a[4], b[4];
#pragma unroll
            for (int i = 0; i < 4; ++i) a[i] = As[kk][tm + 16 * i];
#pragma unroll
            for (int j = 0; j < 4; ++j) b[j] = Bs[kk][tn * 4 + j];
#pragma unroll
            for (int i = 0; i < 4; ++i)
#pragma unroll
                for (int j = 0; j < 4; ++j)
                    acc[i][j] = fmaf(a[i], b[j], acc[i][j]);
        }
    }

    float s1a[4], s2a[4];
#pragma unroll
    for (int j = 0; j < 4; ++j) {
        const int c = nt + tn * 4 + j;
        const float bv = __ldg(&bias[c]);
        float s1 = 0.f, s2 = 0.f;
#pragma unroll
        for (int i = 0; i < 4; ++i) {
            const int m = mt + tm + 16 * i;
            float v = acc[i][j] + bv;
            g_fc[(size_t)m * CH + c] = v;
            s1 += v;
            s2 += v * v;
        }
        s1a[j] = s1; s2a[j] = s2;
    }
    __syncthreads();
    if (tid < 128) sRed[tid] = 0.f;
    __syncthreads();
#pragma unroll
    for (int j = 0; j < 4; ++j) {
        const int cl = tn * 4 + j;
        atomicAdd(&sRed[cl], s1a[j]);
        atomicAdd(&sRed[64 + cl], s2a[j]);
    }
    __syncthreads();
    if (tid < 64) {
        atomicAdd(&g_fsum[nt + tid], sRed[tid]);
        atomicAdd(&g_fsq [nt + tid], sRed[64 + tid]);
    }
}

// ---------------- FC BN + ReLU + IoU head ----------------
__global__ void k_fcbn_iou(const float* __restrict__ gm,
                           const float* __restrict__ bt,
                           const float* __restrict__ iw,
                           const float* __restrict__ ib,
                           float* __restrict__ out)
{
    __shared__ float sred[8];
    const int p = blockIdx.x;
    const int c = threadIdx.x;
    const float invN = 1.f / (float)NROI;
    float m  = g_fsum[c] * invN;
    float v  = g_fsq[c] * invN - m * m;
    float sc = rsqrtf(v + EPS_BN) * __ldg(&gm[c]);
    float sh = __ldg(&bt[c]) - m * sc;
    float x  = fmaxf(fmaf(g_fc[(size_t)p * CH + c], sc, sh), 0.f);
    float t  = x * __ldg(&iw[c]);
#pragma unroll
    for (int o = 16; o; o >>= 1) t += __shfl_xor_sync(0xffffffffu, t, o);
    if ((c & 31) == 0) sred[c >> 5] = t;
    __syncthreads();
    if (c == 0) {
        float s = 0.f;
#pragma unroll
        for (int i = 0; i < 8; ++i) s += sred[i];
        out[p] = s + __ldg(&ib[0]);
    }
}

// ---------------- launch sequence ----------------
extern "C" void kernel_launch(void* const* d_in, const int* in_sizes, int n_in,
                              void* d_out, int out_size)
{
    const float* feat  = (const float*)d_in[0];
    const float* props = (const float*)d_in[1];
    const float* c1w = (const float*)d_in[2];
    const float* c1b = (const float*)d_in[3];
    const float* b1g = (const float*)d_in[4];
    const float* b1b = (const float*)d_in[5];
    const float* c2w = (const float*)d_in[6];
    const float* c2b = (const float*)d_in[7];
    const float* b2g = (const float*)d_in[8];
    const float* b2b = (const float*)d_in[9];
    const float* c3w = (const float*)d_in[10];
    const float* c3b = (const float*)d_in[11];
    const float* b3g = (const float*)d_in[12];
    const float* b3b = (const float*)d_in[13];
    const float* fcw = (const float*)d_in[14];
    const float* fcb = (const float*)d_in[15];
    const float* fbg = (const float*)d_in[16];
    const float* fbb = (const float*)d_in[17];
    const float* iw  = (const float*)d_in[18];
    const float* ib  = (const float*)d_in[19];
    float* out = (float*)d_out;

    const int CONV_SMEM = 69632;   // 4 x [32][136] floats
    cudaFuncSetAttribute(k_conv_m, cudaFuncAttributeMaxDynamicSharedMemorySize, CONV_SMEM);

    const dim3 convGrid(MTOT / 128, 2);          // 324 x 2
    const int  ewBlocks = NIMG * CH * HWSZ / 256;      // 41472 (scalar elementwise)
    const int  bnBlocks = (NIMG * CH * HWSZ / 4) / 256;

    // conv1
    k_wprep<<<KTOT, 256>>>(c1w);
    k_cvtA<<<ewBlocks, 256>>>(feat);
    k_zero_stats<<<1, 256>>>();
    k_conv_m<<<convGrid, 128, CONV_SMEM>>>(c1b);
    k_bnrelu_split<<<ewBlocks, 256>>>(b1g, b1b);
    // conv2
    k_wprep<<<KTOT, 256>>>(c2w);
    k_zero_stats<<<1, 256>>>();
    k_conv_m<<<convGrid, 128, CONV_SMEM>>>(c2b);
    k_bnrelu_split<<<ewBlocks, 256>>>(b2g, b2b);
    // conv3
    k_wprep<<<KTOT, 256>>>(c3w);
    k_zero_stats<<<1, 256>>>();
    k_conv_m<<<convGrid, 128, CONV_SMEM>>>(c3b);
    k_bnrelu_ip<<<bnBlocks, 256>>>(b3g, b3b);

    // integral images (NHWC)
    k_transpose<<<dim3(8, 32, 41), dim3(32, 8)>>>();
    k_cumx<<<NIMG * HH, 256>>>();
    k_cumy<<<NIMG * WW, 256>>>();

    // PrRoI pooling
    k_pool<<<NROI, 256>>>(props);

    // FC + BN + IoU
    k_zero_stats<<<1, 256>>>();
    k_fc<<<dim3(NROI / 64, CH / 64), 256>>>(fcw, fcb);
    k_fcbn_iou<<<NROI, 256>>>(fbg, fbb, iw, ib, out);
}